// round 14
// baseline (speedup 1.0000x reference)
#include <cuda_runtime.h>
#include <cstddef>

#define BB 16
#define SS 512
#define DD 384
#define NT 96          // 96 threads = 96 float4 lanes = one 1536B frame

// Sum a per-thread partial across the 96-thread block; all threads get total.
__device__ __forceinline__ int block_sum_96(int s) {
    const int lane = threadIdx.x & 31, warp = threadIdx.x >> 5;
    #pragma unroll
    for (int off = 16; off; off >>= 1) s += __shfl_down_sync(0xffffffffu, s, off);
    __shared__ int ws[3];
    if (lane == 0) ws[warp] = s;
    __syncthreads();
    return ws[0] + ws[1] + ws[2];
}

// One fused launch, three grid segments (pad first so its uniform work is
// scheduled early and never straggles behind the scatter tail):
//   [0, padBlocks)             : zero padding frames [total_b, L)
//   [padBlocks, +8192)         : scatter — one 96-thread block per token
//   [padBlocks+8192]           : tail (appended out_lengths as float)
// Duration scans use int4 loads; output stores use __stcs (streaming,
// no write-allocate fill — plain stores cost ~2x write traffic).
__global__ void __launch_bounds__(NT) fused_kernel(
    const float* __restrict__ hidden, const int* __restrict__ dur,
    float* __restrict__ out, int L, int padBlocks, int bpb, int tail_n) {
    const int tid = threadIdx.x;
    const int blk = blockIdx.x;
    const int SC = BB * SS;                // 8192 scatter blocks

    if (blk < padBlocks) {
        // ---- padding: zero frames [total_b, L) of batch b ----
        const int b = blk / bpb;
        const int pidx = blk - b * bpb;
        const int4* drow4 = reinterpret_cast<const int4*>(dur + b * SS);

        int s = 0;
        #pragma unroll
        for (int i = tid; i < SS / 4; i += NT) {   // 128 int4 chunks
            const int4 v = drow4[i];
            s += v.x + v.y + v.z + v.w;
        }
        const int total = block_sum_96(s);

        const int warp = tid >> 5, lane = tid & 31;
        const float4 z = make_float4(0.f, 0.f, 0.f, 0.f);
        const int stride = bpb * 3;        // 3 warps per block
        for (int j = pidx * 3 + warp; j < L; j += stride) {
            if (j < total) continue;
            float4* op = reinterpret_cast<float4*>(out + ((size_t)b * L + j) * DD);
            __stcs(op + lane, z);
            __stcs(op + lane + 32, z);
            __stcs(op + lane + 64, z);
        }
        return;
    }

    if (blk < padBlocks + SC) {
        // ---- scatter: frames [excl, excl+d) of batch b <- hidden[b,t] ----
        const int token = blk - padBlocks;
        const int b = token >> 9;
        const int t = token & (SS - 1);
        const int* drow = dur + b * SS;    // 2048B-aligned
        const int d = drow[t];
        if (d == 0) return;

        // exclusive prefix sum of drow[0..t) via int4 loads
        const int4* drow4 = reinterpret_cast<const int4*>(drow);
        const int nf = t >> 2;             // full int4 chunks
        int s = 0;
        for (int i = tid; i < nf; i += NT) {
            const int4 v = drow4[i];
            s += v.x + v.y + v.z + v.w;
        }
        if (tid < (t & 3)) s += drow[(nf << 2) + tid];  // <=3 remainder ints
        const int excl = block_sum_96(s);

        const float4 v =
            reinterpret_cast<const float4*>(hidden + (size_t)token * DD)[tid];
        float4* op = reinterpret_cast<float4*>(
            out + ((size_t)b * L + excl) * DD) + tid;
        for (int f = 0; f < d; f++)
            __stcs(op + f * (DD / 4), v);
        return;
    }

    // ---- tail: out_lengths per batch (as float) after the [B,L,D] tensor ----
    {
        float* tail = out + (size_t)BB * L * DD;
        const int warp = tid >> 5, lane = tid & 31;
        for (int b = warp; b < BB; b += 3) {
            const int4* drow4 = reinterpret_cast<const int4*>(dur + b * SS);
            int s = 0;
            #pragma unroll
            for (int i = lane; i < SS / 4; i += 32) {
                const int4 v = drow4[i];
                s += v.x + v.y + v.z + v.w;
            }
            #pragma unroll
            for (int off = 16; off; off >>= 1)
                s += __shfl_down_sync(0xffffffffu, s, off);
            if (lane == 0 && b < tail_n) tail[b] = (float)s;
        }
        for (int i = BB + tid; i < tail_n; i += NT) tail[i] = 0.f;
    }
}

extern "C" void kernel_launch(void* const* d_in, const int* in_sizes, int n_in,
                              void* d_out, int out_size) {
    // Identify inputs by element count, not order.
    const float* hidden;
    const int*   dur;
    if (in_sizes[0] == BB * SS) {
        dur    = (const int*)d_in[0];
        hidden = (const float*)d_in[1];
    } else {
        hidden = (const float*)d_in[0];
        dur    = (const int*)d_in[1];
    }
    float* out = (float*)d_out;

    const int frame = BB * DD;                 // 6144 floats per frame-slab
    const int L = out_size / frame;            // frames per batch
    const int tail_n = out_size - L * frame;   // 16 if lengths appended

    const int bpb = (L + 95) / 96;             // pad blocks per batch
    const int padBlocks = bpb * BB;

    const int grid = padBlocks + BB * SS + 1;
    fused_kernel<<<grid, NT>>>(hidden, dur, out, L, padBlocks, bpb, tail_n);
}

// round 15
// speedup vs baseline: 1.0063x; 1.0063x over previous
#include <cuda_runtime.h>
#include <cstddef>

#define BB 16
#define SS 512
#define DD 384
#define NT 96          // 96 threads = 96 float4 lanes = one 1536B frame

// Sum a per-thread partial across the 96-thread block; all threads get total.
__device__ __forceinline__ int block_sum_96(int s) {
    const int lane = threadIdx.x & 31, warp = threadIdx.x >> 5;
    #pragma unroll
    for (int off = 16; off; off >>= 1) s += __shfl_down_sync(0xffffffffu, s, off);
    __shared__ int ws[3];
    if (lane == 0) ws[warp] = s;
    __syncthreads();
    return ws[0] + ws[1] + ws[2];
}

// One fused launch, three grid segments (scatter first — this ordering is the
// empirically fastest; pad-first regressed 1.5us):
//   [0, 8192)            : scatter — one 96-thread block per token
//   [8192, +padBlocks)   : zero padding frames [total_b, L)
//   [8192+padBlocks]     : tail (appended out_lengths as float)
// Steady state is DRAM write-drain limited (~5.3 TB/s on the ~99MB output);
// __stcs avoids write-allocate fill, int4 scans keep LSU issue off the
// critical path.
__global__ void __launch_bounds__(NT) fused_kernel(
    const float* __restrict__ hidden, const int* __restrict__ dur,
    float* __restrict__ out, int L, int padBlocks, int bpb, int tail_n) {
    const int tid = threadIdx.x;
    const int blk = blockIdx.x;
    const int SC = BB * SS;                // 8192 scatter blocks

    if (blk < SC) {
        // ---- scatter: frames [excl, excl+d) of batch b <- hidden[b,t] ----
        const int token = blk;
        const int b = token >> 9;
        const int t = token & (SS - 1);
        const int* drow = dur + b * SS;    // 2048B-aligned
        const int d = drow[t];
        if (d == 0) return;

        // Issue the row load FIRST so its latency overlaps the scan below.
        const float4 v =
            reinterpret_cast<const float4*>(hidden + (size_t)token * DD)[tid];

        // exclusive prefix sum of drow[0..t) via int4 loads
        const int4* drow4 = reinterpret_cast<const int4*>(drow);
        const int nf = t >> 2;             // full int4 chunks
        int s = 0;
        for (int i = tid; i < nf; i += NT) {
            const int4 q = drow4[i];
            s += q.x + q.y + q.z + q.w;
        }
        if (tid < (t & 3)) s += drow[(nf << 2) + tid];  // <=3 remainder ints
        const int excl = block_sum_96(s);

        float4* op = reinterpret_cast<float4*>(
            out + ((size_t)b * L + excl) * DD) + tid;
        for (int f = 0; f < d; f++)
            __stcs(op + f * (DD / 4), v);
        return;
    }

    if (blk < SC + padBlocks) {
        // ---- padding: zero frames [total_b, L) of batch b ----
        const int pb = blk - SC;
        const int b = pb / bpb;
        const int pidx = pb - b * bpb;
        const int4* drow4 = reinterpret_cast<const int4*>(dur + b * SS);

        int s = 0;
        #pragma unroll
        for (int i = tid; i < SS / 4; i += NT) {   // 128 int4 chunks
            const int4 q = drow4[i];
            s += q.x + q.y + q.z + q.w;
        }
        const int total = block_sum_96(s);

        const int warp = tid >> 5, lane = tid & 31;
        const float4 z = make_float4(0.f, 0.f, 0.f, 0.f);
        const int stride = bpb * 3;        // 3 warps per block
        for (int j = pidx * 3 + warp; j < L; j += stride) {
            if (j < total) continue;
            float4* op = reinterpret_cast<float4*>(out + ((size_t)b * L + j) * DD);
            __stcs(op + lane, z);
            __stcs(op + lane + 32, z);
            __stcs(op + lane + 64, z);
        }
        return;
    }

    // ---- tail: out_lengths per batch (as float) after the [B,L,D] tensor ----
    {
        float* tail = out + (size_t)BB * L * DD;
        const int warp = tid >> 5, lane = tid & 31;
        for (int b = warp; b < BB; b += 3) {
            const int4* drow4 = reinterpret_cast<const int4*>(dur + b * SS);
            int s = 0;
            #pragma unroll
            for (int i = lane; i < SS / 4; i += 32) {
                const int4 q = drow4[i];
                s += q.x + q.y + q.z + q.w;
            }
            #pragma unroll
            for (int off = 16; off; off >>= 1)
                s += __shfl_down_sync(0xffffffffu, s, off);
            if (lane == 0 && b < tail_n) tail[b] = (float)s;
        }
        for (int i = BB + tid; i < tail_n; i += NT) tail[i] = 0.f;
    }
}

extern "C" void kernel_launch(void* const* d_in, const int* in_sizes, int n_in,
                              void* d_out, int out_size) {
    // Identify inputs by element count, not order.
    const float* hidden;
    const int*   dur;
    if (in_sizes[0] == BB * SS) {
        dur    = (const int*)d_in[0];
        hidden = (const float*)d_in[1];
    } else {
        hidden = (const float*)d_in[0];
        dur    = (const int*)d_in[1];
    }
    float* out = (float*)d_out;

    const int frame = BB * DD;                 // 6144 floats per frame-slab
    const int L = out_size / frame;            // frames per batch
    const int tail_n = out_size - L * frame;   // 16 if lengths appended

    const int bpb = (L + 47) / 48;             // pad blocks per batch
    const int padBlocks = bpb * BB;

    const int grid = BB * SS + padBlocks + 1;
    fused_kernel<<<grid, NT>>>(hidden, dur, out, L, padBlocks, bpb, tail_n);
}

// round 17
// speedup vs baseline: 1.0829x; 1.0761x over previous
#include <cuda_runtime.h>
#include <cstddef>

#define BB 16
#define SS 512
#define DD 384
#define NT 96          // 96 threads = 96 float4 lanes = one 1536B frame

// Sum a per-thread partial across the 96-thread block; all threads get total.
__device__ __forceinline__ int block_sum_96(int s) {
    const int lane = threadIdx.x & 31, warp = threadIdx.x >> 5;
    #pragma unroll
    for (int off = 16; off; off >>= 1) s += __shfl_down_sync(0xffffffffu, s, off);
    __shared__ int ws[3];
    if (lane == 0) ws[warp] = s;
    __syncthreads();
    return ws[0] + ws[1] + ws[2];
}

// One fused launch, three grid segments:
//   [0, 8192)            : scatter — one 96-thread block per token
//   [8192, +padBlocks)   : zero padding frames [total_b, L)
//   [8192+padBlocks]     : tail (appended out_lengths as float)
// Empirically pinned configuration (18.91us across three variants):
//  - scatter-first grid order (pad-first regressed 1.5us)
//  - hidden load AFTER the scan (front-hoisting it raises MLP_p1 and
//    triggers cross-CTA L1tex-queue spread: +1.4us chip-level)
//  - __stcs streaming stores (plain stores: +4us from write-allocate fill)
//  - int4 duration scans (scalar scans push LSU issue onto the critical path)
// Steady state is DRAM write-drain limited (~99MB output @ ~5.3 TB/s).
__global__ void __launch_bounds__(NT) fused_kernel(
    const float* __restrict__ hidden, const int* __restrict__ dur,
    float* __restrict__ out, int L, int padBlocks, int bpb, int tail_n) {
    const int tid = threadIdx.x;
    const int blk = blockIdx.x;
    const int SC = BB * SS;                // 8192 scatter blocks

    if (blk < SC) {
        // ---- scatter: frames [excl, excl+d) of batch b <- hidden[b,t] ----
        const int token = blk;
        const int b = token >> 9;
        const int t = token & (SS - 1);
        const int* drow = dur + b * SS;    // 2048B-aligned
        const int d = drow[t];
        if (d == 0) return;

        // exclusive prefix sum of drow[0..t) via int4 loads
        const int4* drow4 = reinterpret_cast<const int4*>(drow);
        const int nf = t >> 2;             // full int4 chunks
        int s = 0;
        for (int i = tid; i < nf; i += NT) {
            const int4 q = drow4[i];
            s += q.x + q.y + q.z + q.w;
        }
        if (tid < (t & 3)) s += drow[(nf << 2) + tid];  // <=3 remainder ints
        const int excl = block_sum_96(s);

        const float4 v =
            reinterpret_cast<const float4*>(hidden + (size_t)token * DD)[tid];
        float4* op = reinterpret_cast<float4*>(
            out + ((size_t)b * L + excl) * DD) + tid;
        for (int f = 0; f < d; f++)
            __stcs(op + f * (DD / 4), v);
        return;
    }

    if (blk < SC + padBlocks) {
        // ---- padding: zero frames [total_b, L) of batch b ----
        const int pb = blk - SC;
        const int b = pb / bpb;
        const int pidx = pb - b * bpb;
        const int4* drow4 = reinterpret_cast<const int4*>(dur + b * SS);

        int s = 0;
        #pragma unroll
        for (int i = tid; i < SS / 4; i += NT) {   // 128 int4 chunks
            const int4 q = drow4[i];
            s += q.x + q.y + q.z + q.w;
        }
        const int total = block_sum_96(s);

        const int warp = tid >> 5, lane = tid & 31;
        const float4 z = make_float4(0.f, 0.f, 0.f, 0.f);
        const int stride = bpb * 3;        // 3 warps per block
        for (int j = pidx * 3 + warp; j < L; j += stride) {
            if (j < total) continue;
            float4* op = reinterpret_cast<float4*>(out + ((size_t)b * L + j) * DD);
            __stcs(op + lane, z);
            __stcs(op + lane + 32, z);
            __stcs(op + lane + 64, z);
        }
        return;
    }

    // ---- tail: out_lengths per batch (as float) after the [B,L,D] tensor ----
    {
        float* tail = out + (size_t)BB * L * DD;
        const int warp = tid >> 5, lane = tid & 31;
        for (int b = warp; b < BB; b += 3) {
            const int4* drow4 = reinterpret_cast<const int4*>(dur + b * SS);
            int s = 0;
            #pragma unroll
            for (int i = lane; i < SS / 4; i += 32) {
                const int4 q = drow4[i];
                s += q.x + q.y + q.z + q.w;
            }
            #pragma unroll
            for (int off = 16; off; off >>= 1)
                s += __shfl_down_sync(0xffffffffu, s, off);
            if (lane == 0 && b < tail_n) tail[b] = (float)s;
        }
        for (int i = BB + tid; i < tail_n; i += NT) tail[i] = 0.f;
    }
}

extern "C" void kernel_launch(void* const* d_in, const int* in_sizes, int n_in,
                              void* d_out, int out_size) {
    // Identify inputs by element count, not order.
    const float* hidden;
    const int*   dur;
    if (in_sizes[0] == BB * SS) {
        dur    = (const int*)d_in[0];
        hidden = (const float*)d_in[1];
    } else {
        hidden = (const float*)d_in[0];
        dur    = (const int*)d_in[1];
    }
    float* out = (float*)d_out;

    const int frame = BB * DD;                 // 6144 floats per frame-slab
    const int L = out_size / frame;            // frames per batch
    const int tail_n = out_size - L * frame;   // 16 if lengths appended

    const int bpb = (L + 47) / 48;             // pad blocks per batch
    const int padBlocks = bpb * BB;

    const int grid = BB * SS + padBlocks + 1;
    fused_kernel<<<grid, NT>>>(hidden, dur, out, L, padBlocks, bpb, tail_n);
}